// round 2
// baseline (speedup 1.0000x reference)
#include <cuda_runtime.h>
#include <math.h>

#define NTOK  197
#define BATCH 256
#define CDIM  768
#define NH    12
#define HD    64
#define LKEEP 98
#define NP    (NTOK - 1)     // 196
#define NNEW  (LKEEP + 2)    // 100
#define M1    (NTOK * BATCH) // 50432
#define M2    (NNEW * BATCH) // 25600

// ---------------- scratch (device globals; no cudaMalloc allowed) ----------
__device__ float g_ln1 [(size_t)M1 * CDIM];
__device__ float g_qkv [(size_t)M1 * 3 * CDIM];
__device__ float g_att [(size_t)M1 * CDIM];
__device__ float g_xres[(size_t)M1 * CDIM];
__device__ float g_cls [(size_t)BATCH * NP];
__device__ int   g_idx [BATCH * LKEEP];
__device__ int   g_comp[BATCH * LKEEP];
__device__ float g_xnew[(size_t)M2 * CDIM];
__device__ float g_ln2 [(size_t)M2 * CDIM];
__device__ float g_fc  [(size_t)M2 * 4 * CDIM];

// ---------------- layernorm: one block per row of 768 ----------------------
__global__ void ln_kernel(const float* __restrict__ x,
                          const float* __restrict__ gam,
                          const float* __restrict__ bet,
                          float* __restrict__ y)
{
    const int row = blockIdx.x;
    const int t   = threadIdx.x;               // 256 threads, 3 elems each
    const float* xr = x + (size_t)row * CDIM;
    float*       yr = y + (size_t)row * CDIM;

    float v0 = xr[t], v1 = xr[t + 256], v2 = xr[t + 512];
    float s  = v0 + v1 + v2;
    float ss = v0 * v0 + v1 * v1 + v2 * v2;

    __shared__ float red[16];
    #pragma unroll
    for (int o = 16; o; o >>= 1) {
        s  += __shfl_xor_sync(0xffffffffu, s,  o);
        ss += __shfl_xor_sync(0xffffffffu, ss, o);
    }
    const int warp = t >> 5, lane = t & 31;
    if (lane == 0) { red[warp] = s; red[warp + 8] = ss; }
    __syncthreads();
    float S = 0.f, SS = 0.f;
    #pragma unroll
    for (int i = 0; i < 8; i++) { S += red[i]; SS += red[i + 8]; }

    const float mu  = S * (1.f / CDIM);
    const float var = SS * (1.f / CDIM) - mu * mu;
    const float inv = rsqrtf(var + 1e-5f);

    yr[t]       = (v0 - mu) * inv * gam[t]       + bet[t];
    yr[t + 256] = (v1 - mu) * inv * gam[t + 256] + bet[t + 256];
    yr[t + 512] = (v2 - mu) * inv * gam[t + 512] + bet[t + 512];
}

// ---------------- SGEMM: C[M,N] = A[M,K] @ W[N,K]^T + bias (+act)(+res) ----
// 128x128 block tile, BK=8, 256 threads, 8x8 per thread. M%128==N%128==0, K%8==0.
__global__ void __launch_bounds__(256, 2)
sgemm_kernel(const float* __restrict__ A, const float* __restrict__ W,
             const float* __restrict__ bias, const float* __restrict__ res,
             float* __restrict__ C, int M, int Nn, int K, int act)
{
    __shared__ float As[8][132];
    __shared__ float Bs[8][132];

    const int tid  = threadIdx.x;
    const int m0   = blockIdx.y * 128;
    const int n0   = blockIdx.x * 128;
    const int tx   = tid & 15;
    const int ty   = tid >> 4;
    const int lrow = tid >> 1;           // 0..127
    const int lk   = (tid & 1) * 4;      // 0 or 4

    const float* Ap = A + (size_t)(m0 + lrow) * K + lk;
    const float* Wp = W + (size_t)(n0 + lrow) * K + lk;

    float acc[8][8];
    #pragma unroll
    for (int i = 0; i < 8; i++)
        #pragma unroll
        for (int j = 0; j < 8; j++) acc[i][j] = 0.f;

    float4 av = *(const float4*)Ap;
    float4 bv = *(const float4*)Wp;

    for (int k0 = 0; k0 < K; k0 += 8) {
        __syncthreads();
        As[lk + 0][lrow] = av.x; As[lk + 1][lrow] = av.y;
        As[lk + 2][lrow] = av.z; As[lk + 3][lrow] = av.w;
        Bs[lk + 0][lrow] = bv.x; Bs[lk + 1][lrow] = bv.y;
        Bs[lk + 2][lrow] = bv.z; Bs[lk + 3][lrow] = bv.w;
        __syncthreads();
        if (k0 + 8 < K) {                 // prefetch next tile under compute
            av = *(const float4*)(Ap + k0 + 8);
            bv = *(const float4*)(Wp + k0 + 8);
        }
        #pragma unroll
        for (int k = 0; k < 8; k++) {
            float ar[8], br[8];
            float4 t0 = *(const float4*)&As[k][ty * 8];
            float4 t1 = *(const float4*)&As[k][ty * 8 + 4];
            ar[0] = t0.x; ar[1] = t0.y; ar[2] = t0.z; ar[3] = t0.w;
            ar[4] = t1.x; ar[5] = t1.y; ar[6] = t1.z; ar[7] = t1.w;
            float4 u0 = *(const float4*)&Bs[k][tx * 8];
            float4 u1 = *(const float4*)&Bs[k][tx * 8 + 4];
            br[0] = u0.x; br[1] = u0.y; br[2] = u0.z; br[3] = u0.w;
            br[4] = u1.x; br[5] = u1.y; br[6] = u1.z; br[7] = u1.w;
            #pragma unroll
            for (int i = 0; i < 8; i++)
                #pragma unroll
                for (int j = 0; j < 8; j++)
                    acc[i][j] += ar[i] * br[j];
        }
    }

    // epilogue: bias (+quickgelu) (+residual), vectorized stores
    #pragma unroll
    for (int i = 0; i < 8; i++) {
        const int m = m0 + ty * 8 + i;
        const size_t rowb = (size_t)m * Nn + n0 + tx * 8;
        #pragma unroll
        for (int jj = 0; jj < 2; jj++) {
            float4 o;
            float v[4];
            #pragma unroll
            for (int j = 0; j < 4; j++) {
                const int n = n0 + tx * 8 + jj * 4 + j;
                float t = acc[i][jj * 4 + j] + bias[n];
                if (act) t = t / (1.f + __expf(-1.702f * t));
                v[j] = t;
            }
            if (res) {
                float4 r = *(const float4*)(res + rowb + jj * 4);
                v[0] += r.x; v[1] += r.y; v[2] += r.z; v[3] += r.w;
            }
            o.x = v[0]; o.y = v[1]; o.z = v[2]; o.w = v[3];
            *(float4*)(C + rowb + jj * 4) = o;
        }
    }
}

// ---------------- attention: one CTA per (b,h), K/V resident in smem -------
#define KVPAD 65
#define ATT_SMEM ((2 * NTOK * KVPAD + 8 * NTOK + 8 * HD) * (int)sizeof(float))

__global__ void __launch_bounds__(256)
attn_kernel(const float* __restrict__ qkv, float* __restrict__ out)
{
    extern __shared__ float sm[];
    float* Ks = sm;                       // [NTOK][65]
    float* Vs = Ks + NTOK * KVPAD;        // [NTOK][65]
    float* Ps = Vs + NTOK * KVPAD;        // [8][NTOK]
    float* Qs = Ps + 8 * NTOK;            // [8][64]

    const int b = blockIdx.x, h = blockIdx.y;
    const int tid = threadIdx.x, lane = tid & 31, warp = tid >> 5;

    // load K and V tiles (coalesced per 64-float row chunk)
    for (int idx = tid; idx < NTOK * HD; idx += 256) {
        const int j = idx >> 6, d = idx & 63;
        const size_t g = ((size_t)j * BATCH + b) * (3 * CDIM) + h * HD + d;
        Ks[j * KVPAD + d] = qkv[g + CDIM];
        Vs[j * KVPAD + d] = qkv[g + 2 * CDIM];
    }
    __syncthreads();

    for (int i = warp; i < NTOK; i += 8) {
        // stage q_i
        const size_t qg = ((size_t)i * BATCH + b) * (3 * CDIM) + h * HD;
        Qs[warp * HD + lane]      = qkv[qg + lane];
        Qs[warp * HD + lane + 32] = qkv[qg + lane + 32];
        __syncwarp();

        // scores: lane handles j = lane + 32t
        float s[7];
        #pragma unroll
        for (int t = 0; t < 7; t++) s[t] = 0.f;
        #pragma unroll 8
        for (int d = 0; d < HD; d++) {
            const float qd = Qs[warp * HD + d];
            #pragma unroll
            for (int t = 0; t < 7; t++) {
                const int j = lane + t * 32;
                if (j < NTOK) s[t] += qd * Ks[j * KVPAD + d];
            }
        }
        float mx = -1e30f;
        #pragma unroll
        for (int t = 0; t < 7; t++) {
            const int j = lane + t * 32;
            s[t] = (j < NTOK) ? s[t] * 0.125f : -1e30f;
            mx = fmaxf(mx, s[t]);
        }
        #pragma unroll
        for (int o = 16; o; o >>= 1) mx = fmaxf(mx, __shfl_xor_sync(0xffffffffu, mx, o));
        float sum = 0.f;
        #pragma unroll
        for (int t = 0; t < 7; t++) {
            const int j = lane + t * 32;
            const float e = (j < NTOK) ? __expf(s[t] - mx) : 0.f;
            s[t] = e; sum += e;
        }
        #pragma unroll
        for (int o = 16; o; o >>= 1) sum += __shfl_xor_sync(0xffffffffu, sum, o);
        const float inv = 1.f / sum;
        #pragma unroll
        for (int t = 0; t < 7; t++) {
            const int j = lane + t * 32;
            if (j < NTOK) Ps[warp * NTOK + j] = s[t] * inv;
        }
        __syncwarp();

        // o = P @ V : lane owns dims (lane, lane+32)
        float a0 = 0.f, a1 = 0.f;
        #pragma unroll 4
        for (int j = 0; j < NTOK; j++) {
            const float p = Ps[warp * NTOK + j];
            a0 += p * Vs[j * KVPAD + lane];
            a1 += p * Vs[j * KVPAD + lane + 32];
        }
        const size_t og = ((size_t)i * BATCH + b) * CDIM + h * HD;
        out[og + lane]      = a0;
        out[og + lane + 32] = a1;
        __syncwarp();
    }
}

// ---------------- CLS-row attention in fp64 (ranking-critical) --------------
// One block per batch element. Computes cls[b][j] = mean_h softmax(q0.K/8)[j+1]
// entirely in double precision so the top-k ranking matches the true values.
__global__ void __launch_bounds__(256)
cls_attn_kernel(const float* __restrict__ qkv, float* __restrict__ cls)
{
    const int b = blockIdx.x, t = threadIdx.x;
    __shared__ float  q0s[HD];
    __shared__ double sc[NTOK];
    __shared__ double red[2];

    double acc = 0.0;
    for (int h = 0; h < NH; h++) {
        __syncthreads();
        if (t < HD) q0s[t] = qkv[(size_t)b * (3 * CDIM) + h * HD + t];
        __syncthreads();
        if (t < NTOK) {
            const float* kp = qkv + ((size_t)t * BATCH + b) * (3 * CDIM) + CDIM + h * HD;
            double s = 0.0;
            #pragma unroll 8
            for (int d = 0; d < HD; d++) s += (double)q0s[d] * (double)kp[d];
            sc[t] = s * 0.125;
        }
        __syncthreads();
        if (t == 0) {
            double mx = sc[0];
            for (int j = 1; j < NTOK; j++) mx = fmax(mx, sc[j]);
            double sm = 0.0;
            for (int j = 0; j < NTOK; j++) sm += exp(sc[j] - mx);
            red[0] = mx; red[1] = sm;
        }
        __syncthreads();
        if (t >= 1 && t < NTOK)
            acc += exp(sc[t] - red[0]) / red[1];
    }
    if (t >= 1 && t < NTOK)
        cls[(size_t)b * NP + (t - 1)] = (float)(acc * (1.0 / NH));
}

// ---------------- exact stable top-k (value desc, index asc ties) -----------
__global__ void topk_kernel(const float* __restrict__ cls,
                            int* __restrict__ idx, int* __restrict__ comp)
{
    __shared__ float v[NP];
    const int b = blockIdx.x, t = threadIdx.x;
    if (t < NP) v[t] = cls[b * NP + t];
    __syncthreads();
    if (t < NP) {
        const float mv = v[t];
        int r = 0;
        for (int j = 0; j < NP; j++) {
            const float vj = v[j];
            r += (vj > mv) || (vj == mv && j < t);
        }
        if (r < LKEEP) idx[b * LKEEP + r] = t;
        else           comp[b * LKEEP + (r - LKEEP)] = t;
    }
}

// ---------------- build x_new: [cls, topk tokens (desc), fused token] -------
__global__ void gather_kernel(const float* __restrict__ xres,
                              const int* __restrict__ idx,
                              const int* __restrict__ comp,
                              const float* __restrict__ cls,
                              float* __restrict__ xnew)
{
    const int nn = blockIdx.x;   // 0..99
    const int b  = blockIdx.y;
    const int t  = threadIdx.x;  // 256 threads, 3 c's each
    float* dst = xnew + ((size_t)nn * BATCH + b) * CDIM;

    if (nn == 0) {
        const float* src = xres + (size_t)b * CDIM;  // token 0
        dst[t] = src[t]; dst[t + 256] = src[t + 256]; dst[t + 512] = src[t + 512];
    } else if (nn <= LKEEP) {
        const int tok = 1 + idx[b * LKEEP + (nn - 1)];
        const float* src = xres + ((size_t)tok * BATCH + b) * CDIM;
        dst[t] = src[t]; dst[t + 256] = src[t + 256]; dst[t + 512] = src[t + 512];
    } else {
        float a0 = 0.f, a1 = 0.f, a2 = 0.f;
        for (int q = 0; q < LKEEP; q++) {
            const int j = comp[b * LKEEP + q];
            const float w = cls[b * NP + j];
            const float* src = xres + ((size_t)(1 + j) * BATCH + b) * CDIM;
            a0 += src[t] * w; a1 += src[t + 256] * w; a2 += src[t + 512] * w;
        }
        dst[t] = a0; dst[t + 256] = a1; dst[t + 512] = a2;
    }
}

// ---------------- launch ----------------------------------------------------
extern "C" void kernel_launch(void* const* d_in, const int* in_sizes, int n_in,
                              void* d_out, int out_size)
{
    const float* x     = (const float*)d_in[0];
    const float* ln1_g = (const float*)d_in[1];
    const float* ln1_b = (const float*)d_in[2];
    const float* in_w  = (const float*)d_in[3];
    const float* in_b  = (const float*)d_in[4];
    const float* ow    = (const float*)d_in[5];
    const float* ob    = (const float*)d_in[6];
    const float* ln2_g = (const float*)d_in[7];
    const float* ln2_b = (const float*)d_in[8];
    const float* fc_w  = (const float*)d_in[9];
    const float* fc_b  = (const float*)d_in[10];
    const float* pj_w  = (const float*)d_in[11];
    const float* pj_b  = (const float*)d_in[12];
    float* out = (float*)d_out;

    float *ln1, *qkv, *att, *xres, *cls, *xnew, *ln2v, *fcv;
    int *idxp, *compp;
    cudaGetSymbolAddress((void**)&ln1,   g_ln1);
    cudaGetSymbolAddress((void**)&qkv,   g_qkv);
    cudaGetSymbolAddress((void**)&att,   g_att);
    cudaGetSymbolAddress((void**)&xres,  g_xres);
    cudaGetSymbolAddress((void**)&cls,   g_cls);
    cudaGetSymbolAddress((void**)&idxp,  g_idx);
    cudaGetSymbolAddress((void**)&compp, g_comp);
    cudaGetSymbolAddress((void**)&xnew,  g_xnew);
    cudaGetSymbolAddress((void**)&ln2v,  g_ln2);
    cudaGetSymbolAddress((void**)&fcv,   g_fc);

    cudaFuncSetAttribute(attn_kernel, cudaFuncAttributeMaxDynamicSharedMemorySize,
                         ATT_SMEM);

    // 1) ln1
    ln_kernel<<<M1, 256>>>(x, ln1_g, ln1_b, ln1);
    // 2) qkv = ln1 @ in_proj_w^T + b   (50432 x 2304, K=768)
    sgemm_kernel<<<dim3(3 * CDIM / 128, M1 / 128), 256>>>(
        ln1, in_w, in_b, nullptr, qkv, M1, 3 * CDIM, CDIM, 0);
    // 3) attention (per b,h)
    attn_kernel<<<dim3(BATCH, NH), 256, ATT_SMEM>>>(qkv, att);
    // 4) CLS-row attention in fp64 (exact ranking)
    cls_attn_kernel<<<BATCH, 256>>>(qkv, cls);
    // 5) out_proj + residual x  -> xres
    sgemm_kernel<<<dim3(CDIM / 128, M1 / 128), 256>>>(
        att, ow, ob, x, xres, M1, CDIM, CDIM, 0);
    // 6) top-k + complement
    topk_kernel<<<BATCH, 256>>>(cls, idxp, compp);
    // 7) build x_new (100, B, C)
    gather_kernel<<<dim3(NNEW, BATCH), 256>>>(xres, idxp, compp, cls, xnew);
    // 8) ln2
    ln_kernel<<<M2, 256>>>(xnew, ln2_g, ln2_b, ln2v);
    // 9) fc + quickgelu (25600 x 3072, K=768)
    sgemm_kernel<<<dim3(4 * CDIM / 128, M2 / 128), 256>>>(
        ln2v, fc_w, fc_b, nullptr, fcv, M2, 4 * CDIM, CDIM, 1);
    // 10) proj + residual x_new -> out (25600 x 768, K=3072)
    sgemm_kernel<<<dim3(CDIM / 128, M2 / 128), 256>>>(
        fcv, pj_w, pj_b, xnew, out, M2, CDIM, 4 * CDIM, 0);
}